// round 4
// baseline (speedup 1.0000x reference)
#include <cuda_runtime.h>
#include <cstdint>

#define HN 16
#define DD 64
#define BQ 128
#define BK 64
#define NT 256
#define QSCALE 0.1803368801111f   // (1/8) * log2(e)

// smem BYTE offsets
#define B_K    0                  // Ks [64][68] floats
#define B_VT   17408              // Vt [64][68] floats (V transposed: [d][k])
#define B_P    34816              // 8 warps x [16][68] floats
#define B_KSEG 69632              // 64 ints
#define B_CUS  69888              // 64 ints
#define SMEM_BYTES 70144

__device__ __forceinline__ uint32_t f2tf(float x) {
    uint32_t r; asm("cvt.rna.tf32.f32 %0, %1;" : "=r"(r) : "f"(x)); return r;
}
__device__ __forceinline__ float ex2f(float x) {
    float y; asm("ex2.approx.ftz.f32 %0, %1;" : "=f"(y) : "f"(x)); return y;
}
__device__ __forceinline__ void mma8(float* c, const uint32_t* a, uint32_t b0, uint32_t b1) {
    asm volatile("mma.sync.aligned.m16n8k8.row.col.f32.tf32.tf32.f32 "
                 "{%0,%1,%2,%3}, {%4,%5,%6,%7}, {%8,%9}, {%0,%1,%2,%3};"
                 : "+f"(c[0]), "+f"(c[1]), "+f"(c[2]), "+f"(c[3])
                 : "r"(a[0]), "r"(a[1]), "r"(a[2]), "r"(a[3]), "r"(b0), "r"(b1));
}
__device__ __forceinline__ void ldsm4(uint32_t* r, uint32_t addr) {
    asm volatile("ldmatrix.sync.aligned.m8n8.x4.shared.b16 {%0,%1,%2,%3}, [%4];"
                 : "=r"(r[0]), "=r"(r[1]), "=r"(r[2]), "=r"(r[3]) : "r"(addr));
}
__device__ __forceinline__ uint32_t s2u(const void* p) {
    uint32_t a;
    asm("{ .reg .u64 t; cvta.to.shared.u64 t, %1; cvt.u32.u64 %0, t; }" : "=r"(a) : "l"(p));
    return a;
}

// 4x4 transpose among lanes l0..l0+3 (j = lane&3 holds row j of a 4x4 block;
// afterwards holds column j).
__device__ __forceinline__ void trans4(float4& v, int j) {
    float s0 = (j & 2) ? v.x : v.z;
    float s1 = (j & 2) ? v.y : v.w;
    float r0 = __shfl_xor_sync(0xffffffffu, s0, 2);
    float r1 = __shfl_xor_sync(0xffffffffu, s1, 2);
    if (j & 2) { v.x = r0; v.y = r1; } else { v.z = r0; v.w = r1; }
    s0 = (j & 1) ? v.x : v.y;
    s1 = (j & 1) ? v.z : v.w;
    r0 = __shfl_xor_sync(0xffffffffu, s0, 1);
    r1 = __shfl_xor_sync(0xffffffffu, s1, 1);
    if (j & 1) { v.x = r0; v.z = r1; } else { v.y = r0; v.w = r1; }
}

__global__ __launch_bounds__(NT, 2) void varlen_attn_mma(
    const float* __restrict__ qg, const float* __restrict__ kg, const float* __restrict__ vg,
    const int* __restrict__ cuq, const int* __restrict__ cuk,
    float* __restrict__ out, int T, int ncu)
{
    extern __shared__ char smc[];
    const uint32_t sb = s2u(smc);
    float* Ks = (float*)(smc + B_K);
    float* Vt = (float*)(smc + B_VT);
    int* kseg = (int*)(smc + B_KSEG);
    int* cus  = (int*)(smc + B_CUS);

    const int tid  = threadIdx.x;
    const int w    = tid >> 5;
    const int lane = tid & 31;
    const int g    = lane >> 2;
    const int tig  = lane & 3;
    float* Pw = (float*)(smc + B_P) + w * (16 * 68);

    const int h  = blockIdx.y;
    const int q0 = blockIdx.x * BQ;

    // per-lane ldmatrix base addresses (bytes, shared space)
    const uint32_t kb_lane = sb + B_K  + (((lane & 7) * 68 + 4 * (lane >> 3)) << 2);
    const uint32_t vb_lane = sb + B_VT + (((lane & 7) * 68 + 4 * (lane >> 3)) << 2);
    const uint32_t pa_lane = sb + B_P + w * 4352 +
        ((((lane & 7) + 8 * ((lane >> 3) & 1)) * 68 + 4 * (lane >> 4)) << 2);

    if (tid < ncu) cus[tid] = cuk[tid];
    __syncthreads();

    const int t0g = q0 + w * 16 + g;
    const int t1g = t0g + 8;
    int qs0 = 0, qs1 = 0, sfirst = 0, slast = 0;
    {
        const int tl = min(q0 + BQ - 1, T - 1);
        for (int i = 1; i < ncu - 1; i++) {
            int c = cus[i];
            qs0 += (c <= t0g); qs1 += (c <= t1g);
            sfirst += (c <= q0); slast += (c <= tl);
        }
    }
    const int kbeg = cus[sfirst];
    const int kend = cus[slast + 1];

    // ---- Q fragments (registers, whole block) ----
    uint32_t qf[8][4];
    {
        const float* qp0 = qg + (size_t)t0g * (HN * DD) + h * DD;
        const float* qp1 = qg + (size_t)t1g * (HN * DD) + h * DD;
        #pragma unroll
        for (int ks = 0; ks < 8; ks++) {
            int d = ks * 8 + tig;
            qf[ks][0] = f2tf(qp0[d] * QSCALE);
            qf[ks][1] = f2tf(qp1[d] * QSCALE);
            qf[ks][2] = f2tf(qp0[d + 4] * QSCALE);
            qf[ks][3] = f2tf(qp1[d + 4] * QSCALE);
        }
    }

    float oacc[8][4];
    #pragma unroll
    for (int n = 0; n < 8; n++)
        #pragma unroll
        for (int j = 0; j < 4; j++) oacc[n][j] = 0.f;
    float l0 = 0.f, l1 = 0.f;

    for (int kt = (kbeg / BK) * BK; kt < kend; kt += BK) {
        __syncthreads();   // previous iteration's smem readers done

        // ---- load K (natural, tf32) and V (transposed, tf32), kseg ----
        #pragma unroll
        for (int i = 0; i < 4; i++) {
            int idx = tid + i * NT;       // 0..1023
            // K: row-major tile
            {
                int r = idx >> 4, c4 = idx & 15;
                size_t base = (size_t)(kt + r) * (HN * DD) + h * DD + c4 * 4;
                float4 kv = *(const float4*)(kg + base);
                float* kd = Ks + r * 68 + c4 * 4;
                kd[0] = __uint_as_float(f2tf(kv.x));
                kd[1] = __uint_as_float(f2tf(kv.y));
                kd[2] = __uint_as_float(f2tf(kv.z));
                kd[3] = __uint_as_float(f2tf(kv.w));
            }
            // V: transpose 4x4 blocks in registers, store [d][k]
            {
                int lo = idx & 3, mid = (idx >> 2) & 15, hi = idx >> 6;
                int rV = 4 * hi + lo;          // k-row
                int c  = 4 * mid;              // d base
                size_t base = (size_t)(kt + rV) * (HN * DD) + h * DD + c;
                float4 vv = *(const float4*)(vg + base);
                vv.x = __uint_as_float(f2tf(vv.x));
                vv.y = __uint_as_float(f2tf(vv.y));
                vv.z = __uint_as_float(f2tf(vv.z));
                vv.w = __uint_as_float(f2tf(vv.w));
                trans4(vv, lo);
                // now this thread holds Vt row d = c + lo, k-cols 4*hi..4*hi+3
                *(float4*)(Vt + (c + lo) * 68 + 4 * hi) = vv;
            }
        }
        if (tid < BK) {
            int t = kt + tid;
            int s = 0;
            for (int i = 1; i < ncu - 1; i++) s += (cus[i] <= t);
            kseg[tid] = s;
        }
        __syncthreads();

        // ---- S = Q K^T (ldmatrix B-frags) ----
        float sacc[8][4];
        #pragma unroll
        for (int n = 0; n < 8; n++)
            #pragma unroll
            for (int j = 0; j < 4; j++) sacc[n][j] = 0.f;

        #pragma unroll
        for (int n = 0; n < 8; n++) {
            #pragma unroll
            for (int kk = 0; kk < 4; kk++) {
                uint32_t b[4];
                ldsm4(b, kb_lane + n * 2176 + kk * 64);
                mma8(sacc[n], qf[2 * kk],     b[0], b[1]);
                mma8(sacc[n], qf[2 * kk + 1], b[2], b[3]);
            }
        }

        // ---- mask + exp2 + write P ----
        #pragma unroll
        for (int n = 0; n < 8; n++) {
            int kc = n * 8 + 2 * tig;
            int2 ks2 = *(const int2*)&kseg[kc];
            float p00 = (ks2.x == qs0) ? ex2f(sacc[n][0]) : 0.f;
            float p01 = (ks2.y == qs0) ? ex2f(sacc[n][1]) : 0.f;
            float p10 = (ks2.x == qs1) ? ex2f(sacc[n][2]) : 0.f;
            float p11 = (ks2.y == qs1) ? ex2f(sacc[n][3]) : 0.f;
            p00 = __uint_as_float(f2tf(p00));
            p01 = __uint_as_float(f2tf(p01));
            p10 = __uint_as_float(f2tf(p10));
            p11 = __uint_as_float(f2tf(p11));
            l0 += p00 + p01;
            l1 += p10 + p11;
            *(float2*)(Pw + g * 68 + kc)       = make_float2(p00, p01);
            *(float2*)(Pw + (g + 8) * 68 + kc) = make_float2(p10, p11);
        }
        __syncwarp();

        // ---- O += P V (ldmatrix A from P, B from Vt) ----
        #pragma unroll
        for (int kk = 0; kk < 4; kk++) {
            uint32_t a0[4], a1[4];
            ldsm4(a0, pa_lane + (2 * kk) * 32);
            ldsm4(a1, pa_lane + (2 * kk + 1) * 32);
            #pragma unroll
            for (int n = 0; n < 8; n++) {
                uint32_t b[4];
                ldsm4(b, vb_lane + n * 2176 + kk * 64);
                mma8(oacc[n], a0, b[0], b[1]);
                mma8(oacc[n], a1, b[2], b[3]);
            }
        }
    }

    // ---- epilogue ----
    l0 += __shfl_xor_sync(0xffffffffu, l0, 1);
    l0 += __shfl_xor_sync(0xffffffffu, l0, 2);
    l1 += __shfl_xor_sync(0xffffffffu, l1, 1);
    l1 += __shfl_xor_sync(0xffffffffu, l1, 2);
    float i0 = 1.f / l0;
    float i1 = 1.f / l1;

    float* o0 = out + (size_t)t0g * (HN * DD) + h * DD;
    float* o1 = out + (size_t)t1g * (HN * DD) + h * DD;
    #pragma unroll
    for (int n = 0; n < 8; n++) {
        int c = n * 8 + 2 * tig;
        *(float2*)(o0 + c) = make_float2(oacc[n][0] * i0, oacc[n][1] * i0);
        *(float2*)(o1 + c) = make_float2(oacc[n][2] * i1, oacc[n][3] * i1);
    }
}

extern "C" void kernel_launch(void* const* d_in, const int* in_sizes, int n_in,
                              void* d_out, int out_size)
{
    const float* q = (const float*)d_in[0];
    const float* k = (const float*)d_in[1];
    const float* v = (const float*)d_in[2];
    const int* cuq = (const int*)d_in[3];
    const int* cuk = (const int*)d_in[4];

    int T = in_sizes[0] / (HN * DD);
    int ncu = in_sizes[3];

    cudaFuncSetAttribute(varlen_attn_mma,
                         cudaFuncAttributeMaxDynamicSharedMemorySize, SMEM_BYTES);

    dim3 grid((T + BQ - 1) / BQ, HN);
    varlen_attn_mma<<<grid, NT, SMEM_BYTES>>>(q, k, v, cuq, cuk, (float*)d_out, T, ncu);
}